// round 13
// baseline (speedup 1.0000x reference)
#include <cuda_runtime.h>
#include <cstdint>

// Problem constants (fixed by reference: images [8,1,224,224] f32, labels [8,4,224,224] f32)
#define BATCH   8
#define NCLS    4
#define HH      224
#define WW      224
#define RAD     5
#define KS      11
#define BX      16            // threads in x
#define BY      8             // threads in y
#define CPT     2             // centers per thread (x-direction)
#define TW      (BX * CPT)    // 32-wide tile
#define TH      BY            // 8-high tile
#define SW      (TW + 2*RAD)  // 42 (even -> LDS.64 alignment holds per row)
#define SH      (TH + 2*RAD)  // 18
#define TILESX  (WW / TW)     // 7
#define TILESY  (HH / TH)     // 28
#define NTILES  (TILESX * TILESY)  // 196
#define NTHREADS (BX * BY)    // 128

// C1 = -1/100 * log2(e) : intensity-Gaussian slope in log2 domain
#define C1F (-0.014426950408889634f)

// Per-block partials: [b][tile][8] = {num0..3, den.pc0..3}
__device__ float g_scratch[BATCH * NTILES * 8];

__host__ __device__ constexpr float pre_log2(int dy, int dx) {
    // -(dy^2+dx^2)/16 * log2(e)  (spatial Gaussian folded into the exponent)
    return -(float)(dy * dy + dx * dx) * 0.0625f * 1.4426950408889634f;
}

// ---------------- packed f32x2 helpers ----------------
__device__ __forceinline__ uint64_t pk2(float lo, float hi) {
    uint64_t r;
    asm("mov.b64 %0, {%1, %2};" : "=l"(r) : "f"(lo), "f"(hi));
    return r;
}
__device__ __forceinline__ void unpk2(uint64_t v, float& lo, float& hi) {
    asm("mov.b64 {%0, %1}, %2;" : "=f"(lo), "=f"(hi) : "l"(v));
}
__device__ __forceinline__ uint64_t add2(uint64_t a, uint64_t b) {
    uint64_t d; asm("add.rn.f32x2 %0, %1, %2;" : "=l"(d) : "l"(a), "l"(b)); return d;
}
__device__ __forceinline__ uint64_t mul2(uint64_t a, uint64_t b) {
    uint64_t d; asm("mul.rn.f32x2 %0, %1, %2;" : "=l"(d) : "l"(a), "l"(b)); return d;
}
__device__ __forceinline__ uint64_t fma2(uint64_t a, uint64_t b, uint64_t c) {
    uint64_t d; asm("fma.rn.f32x2 %0, %1, %2, %3;" : "=l"(d) : "l"(a), "l"(b), "l"(c)); return d;
}
// {lo: a.hi, hi: b.lo} -- odd-dx operand pair from two even-aligned pairs
__device__ __forceinline__ uint64_t mix2(uint64_t a, uint64_t b) {
    return (a >> 32) | (b << 32);
}
__device__ __forceinline__ float ex2f(float x) {
    float y; asm("ex2.approx.ftz.f32 %0, %1;" : "=f"(y) : "f"(x)); return y;
}

__global__ __launch_bounds__(NTHREADS, 6)
void ncut_main(const float* __restrict__ img, const float* __restrict__ lab) {
    // plane 0 = image (x255, sentinel halo); planes 1..4 = class probabilities
    __shared__ __align__(16) float sm[5][SH][SW];
    __shared__ float red[NTHREADS / 32][8];

    const int tx  = threadIdx.x;            // 0..15
    const int ty  = threadIdx.y;            // 0..7
    const int tid = ty * BX + tx;           // 0..127
    const int b   = blockIdx.z;

    const int gx0 = blockIdx.x * TW - RAD;
    const int gy0 = blockIdx.y * TH - RAD;

    const float* imgb = img + b * (HH * WW);
    const float* labb = lab + b * (NCLS * HH * WW);

    // ---- cooperative tile load (with halo) ----
    #pragma unroll
    for (int i = tid; i < SH * SW; i += NTHREADS) {
        const int ly = i / SW, lxx = i - ly * SW;
        const int gx = gx0 + lxx, gy = gy0 + ly;
        float iv = 1.0e4f;                  // sentinel: ex2 -> 0 == zero-pad mask
        float p0 = 0.f, p1 = 0.f, p2 = 0.f, p3 = 0.f;
        if ((unsigned)gx < (unsigned)WW && (unsigned)gy < (unsigned)HH) {
            const int o = gy * WW + gx;
            iv = imgb[o] * 255.0f;
            p0 = labb[o];
            p1 = labb[o +     HH * WW];
            p2 = labb[o + 2 * HH * WW];
            p3 = labb[o + 3 * HH * WW];
        }
        sm[0][ly][lxx] = iv;
        sm[1][ly][lxx] = p0;
        sm[2][ly][lxx] = p1;
        sm[3][ly][lxx] = p2;
        sm[4][ly][lxx] = p3;
    }
    __syncthreads();

    const int lx = 2 * tx;                  // even -> all LDS.64 bases aligned
    const float Ic0 = sm[0][ty + RAD][lx + RAD];
    const float Ic1 = sm[0][ty + RAD][lx + RAD + 1];
    const uint64_t nIc = pk2(-Ic0, -Ic1);
    const uint64_t C1p = pk2(C1F, C1F);

    uint64_t den = pk2(0.f, 0.f);
    uint64_t acc[NCLS];
    #pragma unroll
    for (int pl = 0; pl < NCLS; pl++) acc[pl] = den;

    #pragma unroll
    for (int dy = 0; dy < KS; dy++) {
        // ---- pass 1: image window -> 11 packed weights for this row ----
        uint64_t win[6];
        {
            const float* rI = &sm[0][ty + dy][lx];
            #pragma unroll
            for (int k = 0; k < 6; k++)
                win[k] = *reinterpret_cast<const uint64_t*>(rI + 2 * k);
        }
        uint64_t wpair[KS];
        #pragma unroll
        for (int dx = 0; dx < KS; dx++) {
            const int k = dx >> 1;
            const uint64_t iv2 = ((dx & 1) == 0) ? win[k] : mix2(win[k], win[k + 1]);
            const float    pre = pre_log2(dy - RAD, dx - RAD);
            const uint64_t dI  = add2(iv2, nIc);
            const uint64_t s   = mul2(dI, dI);
            const uint64_t t   = fma2(s, C1p, pk2(pre, pre));
            float t0, t1; unpk2(t, t0, t1);
            wpair[dx] = pk2(ex2f(t0), ex2f(t1));
        }
        // den: pairwise tree over materialized weights (short dependent chain,
        // lets ptxas pipeline the 11 EX2s without a carried accumulator)
        {
            const uint64_t s01 = add2(wpair[0], wpair[1]);
            const uint64_t s23 = add2(wpair[2], wpair[3]);
            const uint64_t s45 = add2(wpair[4], wpair[5]);
            const uint64_t s67 = add2(wpair[6], wpair[7]);
            const uint64_t s89 = add2(wpair[8], wpair[9]);
            const uint64_t t0  = add2(s01, s23);
            const uint64_t t1  = add2(s45, s67);
            const uint64_t t2  = add2(s89, wpair[10]);
            den = add2(den, add2(add2(t0, t1), t2));
        }
        // ---- pass 2: one label plane at a time (low register pressure) ----
        #pragma unroll
        for (int pl = 0; pl < NCLS; pl++) {
            const float* rp = &sm[pl + 1][ty + dy][lx];
            uint64_t pw[6];
            #pragma unroll
            for (int k = 0; k < 6; k++)
                pw[k] = *reinterpret_cast<const uint64_t*>(rp + 2 * k);
            uint64_t a = acc[pl];
            #pragma unroll
            for (int dx = 0; dx < KS; dx++) {
                const int k = dx >> 1;
                const uint64_t pv = ((dx & 1) == 0) ? pw[k] : mix2(pw[k], pw[k + 1]);
                a = fma2(wpair[dx], pv, a);
            }
            acc[pl] = a;
        }
    }

    // ---- epilogue: both centers' p_f-weighted contributions ----
    float d0, d1;  unpk2(den, d0, d1);
    float v[8];
    #pragma unroll
    for (int pl = 0; pl < NCLS; pl++) {
        float n0, n1; unpk2(acc[pl], n0, n1);
        const float pcA = sm[pl + 1][ty + RAD][lx + RAD];
        const float pcB = sm[pl + 1][ty + RAD][lx + RAD + 1];
        v[pl]        = pcA * n0 + pcB * n1;
        v[pl + NCLS] = pcA * d0 + pcB * d1;
    }

    // ---- deterministic block reduction ----
    #pragma unroll
    for (int o = 16; o > 0; o >>= 1) {
        #pragma unroll
        for (int j = 0; j < 8; j++)
            v[j] += __shfl_down_sync(0xffffffffu, v[j], o);
    }
    const int wid = tid >> 5, lane = tid & 31;
    if (lane == 0) {
        #pragma unroll
        for (int j = 0; j < 8; j++) red[wid][j] = v[j];
    }
    __syncthreads();
    if (tid < 8) {
        float s = 0.f;
        #pragma unroll
        for (int w8 = 0; w8 < NTHREADS / 32; w8++) s += red[w8][tid];
        const int base = ((b * TILESY + blockIdx.y) * TILESX + blockIdx.x) * 8;
        g_scratch[base + tid] = s;
    }
}

__global__ void ncut_finalize(float* __restrict__ out) {
    const int t = threadIdx.x;   // 32 threads: t = b*4 + k
    float r = 0.f;
    {
        const int b = t >> 2, k = t & 3;
        float nd = 0.f, dd = 0.f;
        const float* base = &g_scratch[b * NTILES * 8];
        for (int i = 0; i < NTILES; i++) {
            nd += base[i * 8 + k];
            dd += base[i * 8 + 4 + k];
        }
        r = fabsf(nd / dd);
    }
    #pragma unroll
    for (int o = 16; o > 0; o >>= 1)
        r += __shfl_down_sync(0xffffffffu, r, o);
    if (t == 0)
        out[0] = (float)NCLS - r * (1.0f / (float)BATCH);
}

extern "C" void kernel_launch(void* const* d_in, const int* in_sizes, int n_in,
                              void* d_out, int out_size) {
    const float* images = (const float*)d_in[0];   // [8,1,224,224] f32
    const float* labels = (const float*)d_in[1];   // [8,4,224,224] f32
    float* out = (float*)d_out;                    // scalar f32

    dim3 block(BX, BY, 1);
    dim3 grid(TILESX, TILESY, BATCH);
    ncut_main<<<grid, block>>>(images, labels);
    ncut_finalize<<<1, 32>>>(out);
}

// round 15
// speedup vs baseline: 1.2236x; 1.2236x over previous
#include <cuda_runtime.h>
#include <cstdint>

// Problem constants (fixed by reference: images [8,1,224,224] f32, labels [8,4,224,224] f32)
#define BATCH   8
#define NCLS    4
#define HH      224
#define WW      224
#define RAD     5
#define KS      11
#define BX      16            // threads in x
#define BY      8             // threads in y
#define CPT     2             // centers per thread (x-direction)
#define TW      (BX * CPT)    // 32-wide tile
#define TH      BY            // 8-high tile
#define SW      (TW + 2*RAD)  // 42 (even -> LDS.64 alignment holds per row)
#define SH      (TH + 2*RAD)  // 18
#define TILESX  (WW / TW)     // 7
#define TILESY  (HH / TH)     // 28
#define NTILES  (TILESX * TILESY)  // 196
#define NTHREADS (BX * BY)    // 128

// C1 = -1/100 * log2(e) : intensity-Gaussian slope in log2 domain
#define C1F (-0.014426950408889634f)

// Per-block partials: [b][tile][8] = {num0..3, den.pc0..3}
__device__ float g_scratch[BATCH * NTILES * 8];

__host__ __device__ constexpr float pre_log2(int dy, int dx) {
    // -(dy^2+dx^2)/16 * log2(e)  (spatial Gaussian folded into the exponent)
    return -(float)(dy * dy + dx * dx) * 0.0625f * 1.4426950408889634f;
}

// ---------------- packed f32x2 helpers ----------------
__device__ __forceinline__ uint64_t pk2(float lo, float hi) {
    uint64_t r;
    asm("mov.b64 %0, {%1, %2};" : "=l"(r) : "f"(lo), "f"(hi));
    return r;
}
__device__ __forceinline__ void unpk2(uint64_t v, float& lo, float& hi) {
    asm("mov.b64 {%0, %1}, %2;" : "=f"(lo), "=f"(hi) : "l"(v));
}
__device__ __forceinline__ uint64_t add2(uint64_t a, uint64_t b) {
    uint64_t d; asm("add.rn.f32x2 %0, %1, %2;" : "=l"(d) : "l"(a), "l"(b)); return d;
}
__device__ __forceinline__ uint64_t mul2(uint64_t a, uint64_t b) {
    uint64_t d; asm("mul.rn.f32x2 %0, %1, %2;" : "=l"(d) : "l"(a), "l"(b)); return d;
}
__device__ __forceinline__ uint64_t fma2(uint64_t a, uint64_t b, uint64_t c) {
    uint64_t d; asm("fma.rn.f32x2 %0, %1, %2, %3;" : "=l"(d) : "l"(a), "l"(b), "l"(c)); return d;
}
// {lo: a.hi, hi: b.lo} -- odd-dx operand pair from two even-aligned pairs
__device__ __forceinline__ uint64_t mix2(uint64_t a, uint64_t b) {
    return (a >> 32) | (b << 32);
}
__device__ __forceinline__ float ex2f(float x) {
    float y; asm("ex2.approx.ftz.f32 %0, %1;" : "=f"(y) : "f"(x)); return y;
}

__global__ __launch_bounds__(NTHREADS, 6)
void ncut_main(const float* __restrict__ img, const float* __restrict__ lab) {
    // plane 0 = image (x255, sentinel halo); planes 1..4 = class probabilities
    __shared__ __align__(16) float sm[5][SH][SW];
    __shared__ float red[NTHREADS / 32][8];

    const int tx  = threadIdx.x;            // 0..15
    const int ty  = threadIdx.y;            // 0..7
    const int tid = ty * BX + tx;           // 0..127
    const int b   = blockIdx.z;

    const int gx0 = blockIdx.x * TW - RAD;
    const int gy0 = blockIdx.y * TH - RAD;

    const float* imgb = img + b * (HH * WW);
    const float* labb = lab + b * (NCLS * HH * WW);

    // ---- cooperative tile load (with halo) ----
    #pragma unroll
    for (int i = tid; i < SH * SW; i += NTHREADS) {
        const int ly = i / SW, lxx = i - ly * SW;
        const int gx = gx0 + lxx, gy = gy0 + ly;
        float iv = 1.0e4f;                  // sentinel: ex2 -> 0 == zero-pad mask
        float p0 = 0.f, p1 = 0.f, p2 = 0.f, p3 = 0.f;
        if ((unsigned)gx < (unsigned)WW && (unsigned)gy < (unsigned)HH) {
            const int o = gy * WW + gx;
            iv = imgb[o] * 255.0f;
            p0 = labb[o];
            p1 = labb[o +     HH * WW];
            p2 = labb[o + 2 * HH * WW];
            p3 = labb[o + 3 * HH * WW];
        }
        sm[0][ly][lxx] = iv;
        sm[1][ly][lxx] = p0;
        sm[2][ly][lxx] = p1;
        sm[3][ly][lxx] = p2;
        sm[4][ly][lxx] = p3;
    }
    __syncthreads();

    const int lx = 2 * tx;                  // even -> all LDS.64 bases aligned
    const float Ic0 = sm[0][ty + RAD][lx + RAD];
    const float Ic1 = sm[0][ty + RAD][lx + RAD + 1];
    const uint64_t nIc = pk2(-Ic0, -Ic1);
    const uint64_t C1p = pk2(C1F, C1F);

    uint64_t den = pk2(0.f, 0.f);
    uint64_t acc[NCLS];
    #pragma unroll
    for (int pl = 0; pl < NCLS; pl++) acc[pl] = den;

    #pragma unroll
    for (int dy = 0; dy < KS; dy++) {
        // ---- pass 1: image window -> 11 packed weights for this row ----
        uint64_t win[6];
        {
            const float* rI = &sm[0][ty + dy][lx];
            #pragma unroll
            for (int k = 0; k < 6; k++)
                win[k] = *reinterpret_cast<const uint64_t*>(rI + 2 * k);
        }
        uint64_t wpair[KS];
        #pragma unroll
        for (int dx = 0; dx < KS; dx++) {
            const int k = dx >> 1;
            const uint64_t iv2 = ((dx & 1) == 0) ? win[k] : mix2(win[k], win[k + 1]);
            const float    pre = pre_log2(dy - RAD, dx - RAD);
            const uint64_t dI  = add2(iv2, nIc);
            const uint64_t s   = mul2(dI, dI);
            const uint64_t t   = fma2(s, C1p, pk2(pre, pre));
            float t0, t1; unpk2(t, t0, t1);
            wpair[dx] = pk2(ex2f(t0), ex2f(t1));
        }
        // den: pairwise tree over materialized weights (short dependent chain,
        // lets ptxas pipeline the 11 EX2s without a carried accumulator)
        {
            const uint64_t s01 = add2(wpair[0], wpair[1]);
            const uint64_t s23 = add2(wpair[2], wpair[3]);
            const uint64_t s45 = add2(wpair[4], wpair[5]);
            const uint64_t s67 = add2(wpair[6], wpair[7]);
            const uint64_t s89 = add2(wpair[8], wpair[9]);
            const uint64_t t0  = add2(s01, s23);
            const uint64_t t1  = add2(s45, s67);
            const uint64_t t2  = add2(s89, wpair[10]);
            den = add2(den, add2(add2(t0, t1), t2));
        }
        // ---- pass 2: one label plane at a time (low register pressure) ----
        #pragma unroll
        for (int pl = 0; pl < NCLS; pl++) {
            const float* rp = &sm[pl + 1][ty + dy][lx];
            uint64_t pw[6];
            #pragma unroll
            for (int k = 0; k < 6; k++)
                pw[k] = *reinterpret_cast<const uint64_t*>(rp + 2 * k);
            uint64_t a = acc[pl];
            #pragma unroll
            for (int dx = 0; dx < KS; dx++) {
                const int k = dx >> 1;
                const uint64_t pv = ((dx & 1) == 0) ? pw[k] : mix2(pw[k], pw[k + 1]);
                a = fma2(wpair[dx], pv, a);
            }
            acc[pl] = a;
        }
    }

    // ---- epilogue: both centers' p_f-weighted contributions ----
    float d0, d1;  unpk2(den, d0, d1);
    float v[8];
    #pragma unroll
    for (int pl = 0; pl < NCLS; pl++) {
        float n0, n1; unpk2(acc[pl], n0, n1);
        const float pcA = sm[pl + 1][ty + RAD][lx + RAD];
        const float pcB = sm[pl + 1][ty + RAD][lx + RAD + 1];
        v[pl]        = pcA * n0 + pcB * n1;
        v[pl + NCLS] = pcA * d0 + pcB * d1;
    }

    // ---- deterministic block reduction ----
    #pragma unroll
    for (int o = 16; o > 0; o >>= 1) {
        #pragma unroll
        for (int j = 0; j < 8; j++)
            v[j] += __shfl_down_sync(0xffffffffu, v[j], o);
    }
    const int wid = tid >> 5, lane = tid & 31;
    if (lane == 0) {
        #pragma unroll
        for (int j = 0; j < 8; j++) red[wid][j] = v[j];
    }
    __syncthreads();
    if (tid < 8) {
        float s = 0.f;
        #pragma unroll
        for (int w8 = 0; w8 < NTHREADS / 32; w8++) s += red[w8][tid];
        const int base = ((b * TILESY + blockIdx.y) * TILESX + blockIdx.x) * 8;
        g_scratch[base + tid] = s;
    }
}

// Parallel finalize: 1024 threads. 32 warps x 2 (b,j)-columns each; lanes
// stride the 196 tiles (MLP~7, 32 warps -> load latency hidden), shuffle
// reduce, then warp 0 computes the 32 |num/den| ratios and the scalar.
// Fixed reduction tree -> deterministic across replays.
__global__ __launch_bounds__(1024, 1)
void ncut_finalize(float* __restrict__ out) {
    __shared__ float red[BATCH * 8];        // 64 column sums

    const int tid  = threadIdx.x;
    const int w    = tid >> 5;              // 0..31
    const int lane = tid & 31;

    #pragma unroll
    for (int s = 0; s < 2; s++) {
        const int p = w * 2 + s;            // 0..63
        const int b = p >> 3, j = p & 7;
        const float* base = &g_scratch[b * (NTILES * 8) + j];
        float sum = 0.f;
        for (int i = lane; i < NTILES; i += 32)
            sum += base[i * 8];
        #pragma unroll
        for (int o = 16; o > 0; o >>= 1)
            sum += __shfl_down_sync(0xffffffffu, sum, o);
        if (lane == 0) red[p] = sum;
    }
    __syncthreads();

    if (w == 0) {
        const int b = lane >> 2, k = lane & 3;   // lane = b*4 + k
        float r = fabsf(red[b * 8 + k] / red[b * 8 + 4 + k]);
        #pragma unroll
        for (int o = 16; o > 0; o >>= 1)
            r += __shfl_down_sync(0xffffffffu, r, o);
        if (lane == 0)
            out[0] = (float)NCLS - r * (1.0f / (float)BATCH);
    }
}

extern "C" void kernel_launch(void* const* d_in, const int* in_sizes, int n_in,
                              void* d_out, int out_size) {
    const float* images = (const float*)d_in[0];   // [8,1,224,224] f32
    const float* labels = (const float*)d_in[1];   // [8,4,224,224] f32
    float* out = (float*)d_out;                    // scalar f32

    dim3 block(BX, BY, 1);
    dim3 grid(TILESX, TILESY, BATCH);
    ncut_main<<<grid, block>>>(images, labels);
    ncut_finalize<<<1, 1024>>>(out);
}